// round 11
// baseline (speedup 1.0000x reference)
#include <cuda_runtime.h>
#include <cuda_bf16.h>
#include <math.h>

#define DD   128
#define CC   64
#define LL   64
#define KSPLIT 384            // [hi | lo | hi] packed K (bf16 elements)
#define BT   128              // b rows per CTA
#define NTT  256              // l cols per CTA (4 categories)
#define KC   96               // k elements per chunk (192 bytes/row)
#define ROWB 192              // smem row bytes
#define NCHUNK 4
#define NSTAGE 3
#define A_BYTES (128 * ROWB)  // 24KB
#define B_BYTES (256 * ROWB)  // 48KB
#define STAGE_BYTES (A_BYTES + B_BYTES)   // 72KB

// ---- device scratch (allocation-free) ----
__device__ __nv_bfloat16 gA[65536ull * KSPLIT];   // ~50 MB
__device__ __nv_bfloat16 gB[4096ull  * KSPLIT];

__device__ __forceinline__ unsigned smem_u32(const void* p) {
    unsigned a;
    asm("{ .reg .u64 t; cvta.to.shared.u64 t, %1; cvt.u32.u64 %0, t; }" : "=r"(a) : "l"(p));
    return a;
}
template<int N> __device__ __forceinline__ void cp_wait() {
    asm volatile("cp.async.wait_group %0;" :: "n"(N) : "memory");
}

// ---------------- prep: normalize + bf16 split-pack ----------------
template<int ROWS_TOTAL>
__global__ void split_pack_kernel(const float* __restrict__ src, __nv_bfloat16* __restrict__ dst) {
    int row  = blockIdx.x * 8 + (threadIdx.x >> 5);
    if (row >= ROWS_TOTAL) return;
    int lane = threadIdx.x & 31;
    float4 v = *reinterpret_cast<const float4*>(src + (size_t)row * DD + lane * 4);
    float s = v.x * v.x + v.y * v.y + v.z * v.z + v.w * v.w;
#pragma unroll
    for (int o = 16; o > 0; o >>= 1) s += __shfl_xor_sync(0xffffffffu, s, o);
    float inv = 1.0f / fmaxf(sqrtf(s), 1e-8f);

    float f[4] = {v.x * inv, v.y * inv, v.z * inv, v.w * inv};
    unsigned short hi[4], lo[4];
#pragma unroll
    for (int i = 0; i < 4; i++) {
        __nv_bfloat16 h = __float2bfloat16_rn(f[i]);
        __nv_bfloat16 l = __float2bfloat16_rn(f[i] - __bfloat162float(h));
        hi[i] = __bfloat16_as_ushort(h);
        lo[i] = __bfloat16_as_ushort(l);
    }
    uint2 hp = make_uint2((unsigned)hi[0] | ((unsigned)hi[1] << 16),
                          (unsigned)hi[2] | ((unsigned)hi[3] << 16));
    uint2 lp = make_uint2((unsigned)lo[0] | ((unsigned)lo[1] << 16),
                          (unsigned)lo[2] | ((unsigned)lo[3] << 16));
    size_t base = (size_t)row * KSPLIT + lane * 4;
    if (ROWS_TOTAL == 65536) {          // A pack: [hi | lo | hi]
        *reinterpret_cast<uint2*>(dst + base)       = hp;
        *reinterpret_cast<uint2*>(dst + base + 128) = lp;
        *reinterpret_cast<uint2*>(dst + base + 256) = hp;
    } else {                            // B pack: [hi | hi | lo]
        *reinterpret_cast<uint2*>(dst + base)       = hp;
        *reinterpret_cast<uint2*>(dst + base + 128) = hp;
        *reinterpret_cast<uint2*>(dst + base + 256) = lp;
    }
}

__global__ void init_counts_kernel(const float* __restrict__ leaf, float* __restrict__ counts) {
    int i = blockIdx.x * blockDim.x + threadIdx.x;
    if (i < CC * LL) counts[i] = leaf[i];
}

// ---------------- main fused GEMM + max/argmax (mma.sync) ----------------
// 512 threads, 16 warps (4m x 4n), warp tile 32x64, CTA tile 128x256
__global__ __launch_bounds__(512, 1)
void cosmax_mma_kernel(float* __restrict__ cos_out, float* __restrict__ counts) {
    extern __shared__ char smem[];
    __shared__ float hist[256];
    const unsigned sb = smem_u32(smem);
    const int tid  = threadIdx.x;
    const int lane = tid & 31;
    const int wid  = tid >> 5;
    const int wm   = wid >> 2;     // 0..3 : warp row (32 b-rows)
    const int wn   = wid & 3;      // 0..3 : category within CTA (64 cols)
    const int b0   = blockIdx.x * BT;
    const int l0   = blockIdx.y * NTT;
    if (tid < 256) hist[tid] = 0.0f;

    float acc[2][8][4];
#pragma unroll
    for (int mt = 0; mt < 2; mt++)
#pragma unroll
        for (int nt = 0; nt < 8; nt++)
#pragma unroll
            for (int c = 0; c < 4; c++) acc[mt][nt][c] = 0.0f;

    // loader mapping (warp-contiguous rows):
    //  A: 4 thr/row, each thread 48B contiguous (3 x 16B) -> warp covers 8 full rows
    //  B: 2 thr/row, each thread 96B contiguous (6 x 16B) -> warp covers 16 full rows
    const int ra = tid >> 2;  const unsigned ca0 = (unsigned)(tid & 3) * 48u;
    const int rb = tid >> 1;  const unsigned cb0 = (unsigned)(tid & 1) * 96u;
    const unsigned axor = (unsigned)(ra & 7) << 4;
    const unsigned bxor = (unsigned)(rb & 7) << 4;

#define ISSUE(c)                                                                           \
    {                                                                                      \
        unsigned s_ = sb + ((c) % NSTAGE) * STAGE_BYTES;                                   \
        const char* ga_ = (const char*)gA + ((size_t)(b0 + ra) * KSPLIT + (c) * KC) * 2;   \
        const char* gb_ = (const char*)gB + ((size_t)(l0 + rb) * KSPLIT + (c) * KC) * 2;   \
        _Pragma("unroll")                                                                  \
        for (int j = 0; j < 3; j++) {                                                      \
            unsigned off_ = (unsigned)ra * ROWB + ca0 + (unsigned)j * 16u;                 \
            asm volatile("cp.async.cg.shared.global [%0],[%1],16;"                         \
                         :: "r"(s_ + (off_ ^ axor)), "l"(ga_ + ca0 + j * 16) : "memory");  \
        }                                                                                  \
        _Pragma("unroll")                                                                  \
        for (int j = 0; j < 6; j++) {                                                      \
            unsigned off_ = (unsigned)rb * ROWB + cb0 + (unsigned)j * 16u;                 \
            asm volatile("cp.async.cg.shared.global [%0],[%1],16;"                         \
                         :: "r"(s_ + A_BYTES + (off_ ^ bxor)), "l"(gb_ + cb0 + j * 16) : "memory"); \
        }                                                                                  \
        asm volatile("cp.async.commit_group;" ::: "memory");                               \
    }

    ISSUE(0); ISSUE(1);

#pragma unroll
    for (int c = 0; c < NCHUNK; c++) {
        if (c < NCHUNK - 1) cp_wait<1>();
        else                cp_wait<0>();
        __syncthreads();                 // stage c ready; stage (c-1) fully consumed
        if (c + 2 < NCHUNK) ISSUE(c + 2);

        const unsigned s = sb + (c % NSTAGE) * STAGE_BYTES;
#pragma unroll
        for (int ks = 0; ks < 6; ks++) {
            unsigned af[2][4];
#pragma unroll
            for (int mt = 0; mt < 2; mt++) {
                int row = wm * 32 + mt * 16 + (lane & 15);
                unsigned off = (unsigned)row * ROWB + (unsigned)ks * 32u + ((lane >> 4) * 16u);
                unsigned addr = s + (off ^ ((unsigned)(row & 7) << 4));
                asm volatile("ldmatrix.sync.aligned.m8n8.x4.shared.b16 {%0,%1,%2,%3},[%4];"
                             : "=r"(af[mt][0]), "=r"(af[mt][1]), "=r"(af[mt][2]), "=r"(af[mt][3])
                             : "r"(addr));
            }
            unsigned bf[8][2];
#pragma unroll
            for (int np = 0; np < 4; np++) {
                int row = wn * 64 + np * 16 + ((lane & 16) >> 1) + (lane & 7);
                unsigned off = (unsigned)row * ROWB + (unsigned)ks * 32u + ((lane & 8) ? 16u : 0u);
                unsigned addr = s + A_BYTES + (off ^ ((unsigned)(row & 7) << 4));
                asm volatile("ldmatrix.sync.aligned.m8n8.x4.shared.b16 {%0,%1,%2,%3},[%4];"
                             : "=r"(bf[2*np][0]), "=r"(bf[2*np][1]),
                               "=r"(bf[2*np+1][0]), "=r"(bf[2*np+1][1])
                             : "r"(addr));
            }
#pragma unroll
            for (int mt = 0; mt < 2; mt++)
#pragma unroll
                for (int nt = 0; nt < 8; nt++)
                    asm volatile(
                        "mma.sync.aligned.m16n8k16.row.col.f32.bf16.bf16.f32 "
                        "{%0,%1,%2,%3},{%4,%5,%6,%7},{%8,%9},{%0,%1,%2,%3};"
                        : "+f"(acc[mt][nt][0]), "+f"(acc[mt][nt][1]),
                          "+f"(acc[mt][nt][2]), "+f"(acc[mt][nt][3])
                        : "r"(af[mt][0]), "r"(af[mt][1]), "r"(af[mt][2]), "r"(af[mt][3]),
                          "r"(bf[nt][0]), "r"(bf[nt][1]));
        }
    }

    // ---- epilogue: in-register max/argmax over this warp's 64-col category ----
    const int qcol = (lane & 3) * 2;
#pragma unroll
    for (int mt = 0; mt < 2; mt++) {
#pragma unroll
        for (int h = 0; h < 2; h++) {
            float m = __int_as_float(0xff800000);
            int arg = 0;
#pragma unroll
            for (int nt = 0; nt < 8; nt++) {
                float v0 = acc[mt][nt][2 * h];
                float v1 = acc[mt][nt][2 * h + 1];
                int c0 = nt * 8 + qcol;
                if (v0 > m) { m = v0; arg = c0; }
                if (v1 > m) { m = v1; arg = c0 + 1; }
            }
#pragma unroll
            for (int off = 1; off <= 2; off <<= 1) {
                float om = __shfl_xor_sync(0xffffffffu, m, off);
                int   oa = __shfl_xor_sync(0xffffffffu, arg, off);
                if (om > m || (om == m && oa < arg)) { m = om; arg = oa; }
            }
            if ((lane & 3) == 0) {
                int row = b0 + wm * 32 + mt * 16 + h * 8 + (lane >> 2);
                cos_out[(size_t)row * CC + blockIdx.y * 4 + wn] = m;
                atomicAdd(&hist[wn * LL + arg], 1.0f);
            }
        }
    }
    __syncthreads();
    if (tid < 256) {
        float v = hist[tid];
        if (v != 0.0f)
            atomicAdd(&counts[(blockIdx.y * 4 + (tid >> 6)) * LL + (tid & 63)], v);
    }
#undef ISSUE
}

extern "C" void kernel_launch(void* const* d_in, const int* in_sizes, int n_in,
                              void* d_out, int out_size) {
    const float* x    = (const float*)d_in[0];
    const float* e    = (const float*)d_in[1];
    const float* leaf = (const float*)d_in[2];
    const int B = in_sizes[0] / DD;            // 65536

    float* cos_out = (float*)d_out;            // [B, C]
    float* counts  = cos_out + (size_t)B * CC; // [C, L]

    __nv_bfloat16 *pA, *pB;
    cudaGetSymbolAddress((void**)&pA, gA);
    cudaGetSymbolAddress((void**)&pB, gB);

    cudaFuncSetAttribute(cosmax_mma_kernel,
                         cudaFuncAttributeMaxDynamicSharedMemorySize, NSTAGE * STAGE_BYTES);

    split_pack_kernel<65536><<<B / 8, 256>>>(x, pA);
    split_pack_kernel<4096><<<(CC * LL) / 8, 256>>>(e, pB);
    init_counts_kernel<<<(CC * LL + 255) / 256, 256>>>(leaf, counts);

    dim3 grid(B / BT, (CC * LL) / NTT);        // (512, 16)
    cosmax_mma_kernel<<<grid, 512, NSTAGE * STAGE_BYTES>>>(cos_out, counts);
}

// round 13
// speedup vs baseline: 2.9752x; 2.9752x over previous
#include <cuda_runtime.h>
#include <cuda_bf16.h>
#include <math.h>

#define DD   128
#define CC   64
#define LL   64
#define KSPLIT 384            // [hi | lo | hi] packed K (bf16 elements)
#define BT   128              // b rows per CTA
#define NTT  128              // l cols per CTA (2 categories)
#define KC   64               // k per chunk (128B rows)
#define NCHUNK 6
#define NSTAGE 3
#define A_BYTES 16384         // 128 rows x 128B
#define B_BYTES 16384         // 128 rows x 128B
#define STAGE_BYTES (A_BYTES + B_BYTES)   // 32KB

// ---- device scratch (allocation-free) ----
__device__ __nv_bfloat16 gA[65536ull * KSPLIT];   // ~50 MB
__device__ __nv_bfloat16 gB[4096ull  * KSPLIT];

__device__ __forceinline__ unsigned smem_u32(const void* p) {
    unsigned a;
    asm("{ .reg .u64 t; cvta.to.shared.u64 t, %1; cvt.u32.u64 %0, t; }" : "=r"(a) : "l"(p));
    return a;
}
template<int N> __device__ __forceinline__ void cp_wait() {
    asm volatile("cp.async.wait_group %0;" :: "n"(N) : "memory");
}

// ---------------- prep: normalize + bf16 split-pack ----------------
template<int ROWS_TOTAL>
__global__ void split_pack_kernel(const float* __restrict__ src, __nv_bfloat16* __restrict__ dst) {
    int row  = blockIdx.x * 8 + (threadIdx.x >> 5);
    if (row >= ROWS_TOTAL) return;
    int lane = threadIdx.x & 31;
    float4 v = *reinterpret_cast<const float4*>(src + (size_t)row * DD + lane * 4);
    float s = v.x * v.x + v.y * v.y + v.z * v.z + v.w * v.w;
#pragma unroll
    for (int o = 16; o > 0; o >>= 1) s += __shfl_xor_sync(0xffffffffu, s, o);
    float inv = 1.0f / fmaxf(sqrtf(s), 1e-8f);

    float f[4] = {v.x * inv, v.y * inv, v.z * inv, v.w * inv};
    unsigned short hi[4], lo[4];
#pragma unroll
    for (int i = 0; i < 4; i++) {
        __nv_bfloat16 h = __float2bfloat16_rn(f[i]);
        __nv_bfloat16 l = __float2bfloat16_rn(f[i] - __bfloat162float(h));
        hi[i] = __bfloat16_as_ushort(h);
        lo[i] = __bfloat16_as_ushort(l);
    }
    uint2 hp = make_uint2((unsigned)hi[0] | ((unsigned)hi[1] << 16),
                          (unsigned)hi[2] | ((unsigned)hi[3] << 16));
    uint2 lp = make_uint2((unsigned)lo[0] | ((unsigned)lo[1] << 16),
                          (unsigned)lo[2] | ((unsigned)lo[3] << 16));
    size_t base = (size_t)row * KSPLIT + lane * 4;
    if (ROWS_TOTAL == 65536) {          // A pack: [hi | lo | hi]
        *reinterpret_cast<uint2*>(dst + base)       = hp;
        *reinterpret_cast<uint2*>(dst + base + 128) = lp;
        *reinterpret_cast<uint2*>(dst + base + 256) = hp;
    } else {                            // B pack: [hi | hi | lo]
        *reinterpret_cast<uint2*>(dst + base)       = hp;
        *reinterpret_cast<uint2*>(dst + base + 128) = hp;
        *reinterpret_cast<uint2*>(dst + base + 256) = lp;
    }
}

__global__ void init_counts_kernel(const float* __restrict__ leaf, float* __restrict__ counts) {
    int i = blockIdx.x * blockDim.x + threadIdx.x;
    if (i < CC * LL) counts[i] = leaf[i];
}

// ---------------- main fused GEMM + max/argmax (mma.sync) ----------------
// 256 threads, 8 warps (4m x 2n), warp tile 32x64, CTA tile 128x128, 2 CTAs/SM
__global__ __launch_bounds__(256, 2)
void cosmax_mma_kernel(float* __restrict__ cos_out, float* __restrict__ counts) {
    extern __shared__ char smem[];
    __shared__ float hist[128];
    const unsigned sb = smem_u32(smem);
    const int tid  = threadIdx.x;
    const int lane = tid & 31;
    const int wid  = tid >> 5;
    const int wm   = wid >> 1;     // 0..3 : warp row (32 b-rows)
    const int wn   = wid & 1;      // 0..1 : category within CTA (64 cols)
    const int b0   = blockIdx.x * BT;
    const int l0   = blockIdx.y * NTT;
    if (tid < 128) hist[tid] = 0.0f;

    float acc[2][8][4];
#pragma unroll
    for (int mt = 0; mt < 2; mt++)
#pragma unroll
        for (int nt = 0; nt < 8; nt++)
#pragma unroll
            for (int c = 0; c < 4; c++) acc[mt][nt][c] = 0.0f;

    // Loader: chunk index idx = j*256 + tid over 1024 16B-chunks per matrix.
    // 32 consecutive lanes = 32 consecutive chunks = 4 complete 128B rows:
    // coalesced global reads AND dense swizzled smem store wavefronts.
#define ISSUE(c)                                                                          \
    {                                                                                     \
        unsigned s_ = sb + ((c) % NSTAGE) * STAGE_BYTES;                                  \
        _Pragma("unroll")                                                                 \
        for (int j = 0; j < 4; j++) {                                                     \
            unsigned idx  = (unsigned)j * 256u + (unsigned)tid;                           \
            unsigned row  = idx >> 3;                                                     \
            unsigned col  = (idx & 7) * 16u;                                              \
            unsigned off_ = row * 128u + col;                                             \
            unsigned sw_  = off_ ^ ((row & 7) << 4);                                      \
            const char* ga_ = (const char*)gA + ((size_t)(b0 + row) * KSPLIT + (c) * KC) * 2 + col; \
            const char* gb_ = (const char*)gB + ((size_t)(l0 + row) * KSPLIT + (c) * KC) * 2 + col; \
            asm volatile("cp.async.cg.shared.global [%0],[%1],16;"                        \
                         :: "r"(s_ + sw_), "l"(ga_) : "memory");                          \
            asm volatile("cp.async.cg.shared.global [%0],[%1],16;"                        \
                         :: "r"(s_ + A_BYTES + sw_), "l"(gb_) : "memory");                \
        }                                                                                 \
        asm volatile("cp.async.commit_group;" ::: "memory");                              \
    }

    ISSUE(0); ISSUE(1);

#pragma unroll
    for (int c = 0; c < NCHUNK; c++) {
        if (c < NCHUNK - 1) cp_wait<1>();
        else                cp_wait<0>();
        __syncthreads();                 // stage c ready; stage (c-1) fully consumed
        if (c + 2 < NCHUNK) ISSUE(c + 2);

        const unsigned s = sb + (c % NSTAGE) * STAGE_BYTES;
#pragma unroll
        for (int ks = 0; ks < 4; ks++) {
            unsigned af[2][4];
#pragma unroll
            for (int mt = 0; mt < 2; mt++) {
                int row = wm * 32 + mt * 16 + (lane & 15);
                unsigned off = (unsigned)row * 128u + (unsigned)ks * 32u + ((lane >> 4) * 16u);
                unsigned addr = s + (off ^ ((unsigned)(row & 7) << 4));
                asm volatile("ldmatrix.sync.aligned.m8n8.x4.shared.b16 {%0,%1,%2,%3},[%4];"
                             : "=r"(af[mt][0]), "=r"(af[mt][1]), "=r"(af[mt][2]), "=r"(af[mt][3])
                             : "r"(addr));
            }
            unsigned bf[8][2];
#pragma unroll
            for (int np = 0; np < 4; np++) {
                int row = wn * 64 + np * 16 + ((lane & 16) >> 1) + (lane & 7);
                unsigned off = (unsigned)row * 128u + (unsigned)ks * 32u + ((lane & 8) ? 16u : 0u);
                unsigned addr = s + A_BYTES + (off ^ ((unsigned)(row & 7) << 4));
                asm volatile("ldmatrix.sync.aligned.m8n8.x4.shared.b16 {%0,%1,%2,%3},[%4];"
                             : "=r"(bf[2*np][0]), "=r"(bf[2*np][1]),
                               "=r"(bf[2*np+1][0]), "=r"(bf[2*np+1][1])
                             : "r"(addr));
            }
#pragma unroll
            for (int mt = 0; mt < 2; mt++)
#pragma unroll
                for (int nt = 0; nt < 8; nt++)
                    asm volatile(
                        "mma.sync.aligned.m16n8k16.row.col.f32.bf16.bf16.f32 "
                        "{%0,%1,%2,%3},{%4,%5,%6,%7},{%8,%9},{%0,%1,%2,%3};"
                        : "+f"(acc[mt][nt][0]), "+f"(acc[mt][nt][1]),
                          "+f"(acc[mt][nt][2]), "+f"(acc[mt][nt][3])
                        : "r"(af[mt][0]), "r"(af[mt][1]), "r"(af[mt][2]), "r"(af[mt][3]),
                          "r"(bf[nt][0]), "r"(bf[nt][1]));
        }
    }

    // ---- epilogue: in-register max/argmax over this warp's 64-col category ----
    const int qcol = (lane & 3) * 2;
#pragma unroll
    for (int mt = 0; mt < 2; mt++) {
#pragma unroll
        for (int h = 0; h < 2; h++) {
            float m = __int_as_float(0xff800000);
            int arg = 0;
#pragma unroll
            for (int nt = 0; nt < 8; nt++) {
                float v0 = acc[mt][nt][2 * h];
                float v1 = acc[mt][nt][2 * h + 1];
                int c0 = nt * 8 + qcol;
                if (v0 > m) { m = v0; arg = c0; }
                if (v1 > m) { m = v1; arg = c0 + 1; }
            }
#pragma unroll
            for (int off = 1; off <= 2; off <<= 1) {
                float om = __shfl_xor_sync(0xffffffffu, m, off);
                int   oa = __shfl_xor_sync(0xffffffffu, arg, off);
                if (om > m || (om == m && oa < arg)) { m = om; arg = oa; }
            }
            if ((lane & 3) == 0) {
                int row = b0 + wm * 32 + mt * 16 + h * 8 + (lane >> 2);
                cos_out[(size_t)row * CC + blockIdx.y * 2 + wn] = m;
                atomicAdd(&hist[wn * LL + arg], 1.0f);
            }
        }
    }
    __syncthreads();
    if (tid < 128) {
        float v = hist[tid];
        if (v != 0.0f)
            atomicAdd(&counts[(blockIdx.y * 2 + (tid >> 6)) * LL + (tid & 63)], v);
    }
#undef ISSUE
}

extern "C" void kernel_launch(void* const* d_in, const int* in_sizes, int n_in,
                              void* d_out, int out_size) {
    const float* x    = (const float*)d_in[0];
    const float* e    = (const float*)d_in[1];
    const float* leaf = (const float*)d_in[2];
    const int B = in_sizes[0] / DD;            // 65536

    float* cos_out = (float*)d_out;            // [B, C]
    float* counts  = cos_out + (size_t)B * CC; // [C, L]

    __nv_bfloat16 *pA, *pB;
    cudaGetSymbolAddress((void**)&pA, gA);
    cudaGetSymbolAddress((void**)&pB, gB);

    cudaFuncSetAttribute(cosmax_mma_kernel,
                         cudaFuncAttributeMaxDynamicSharedMemorySize, NSTAGE * STAGE_BYTES);

    split_pack_kernel<65536><<<B / 8, 256>>>(x, pA);
    split_pack_kernel<4096><<<(CC * LL) / 8, 256>>>(e, pB);
    init_counts_kernel<<<(CC * LL + 255) / 256, 256>>>(leaf, counts);

    dim3 grid(B / BT, (CC * LL) / NTT);        // (512, 32)
    cosmax_mma_kernel<<<grid, 256, NSTAGE * STAGE_BYTES>>>(cos_out, counts);
}

// round 14
// speedup vs baseline: 3.2588x; 1.0953x over previous
#include <cuda_runtime.h>
#include <cuda_bf16.h>
#include <math.h>

#define DD   128
#define CC   64
#define LL   64
#define KSP  256              // packed K: [hi | lo]
#define BT   128              // b rows per CTA
#define NTT  128              // l cols per CTA (2 categories)
#define SLAB 16384            // 128 rows x 128B
// smem: 4 pinned slabs [Ahi0|Ahi1|Bhi0|Bhi1] + 3-stage ring
#define PIN0 0
#define PIN1 (1 * SLAB)
#define PIN2 (2 * SLAB)
#define PIN3 (3 * SLAB)
#define RING0 (4 * SLAB)
#define RING1 (5 * SLAB)
#define RING2 (6 * SLAB)
#define SMEM_TOTAL (7 * SLAB)   // 112KB

// ---- device scratch (allocation-free) ----
__device__ __nv_bfloat16 gA[65536ull * KSP];   // 32 MB
__device__ __nv_bfloat16 gB[4096ull  * KSP];   // 2 MB

__device__ __forceinline__ unsigned smem_u32(const void* p) {
    unsigned a;
    asm("{ .reg .u64 t; cvta.to.shared.u64 t, %1; cvt.u32.u64 %0, t; }" : "=r"(a) : "l"(p));
    return a;
}
template<int N> __device__ __forceinline__ void cp_wait() {
    asm volatile("cp.async.wait_group %0;" :: "n"(N) : "memory");
}

// ---------------- prep: normalize + bf16 split-pack [hi|lo] ----------------
template<int ROWS_TOTAL>
__global__ void split_pack_kernel(const float* __restrict__ src, __nv_bfloat16* __restrict__ dst) {
    int row  = blockIdx.x * 8 + (threadIdx.x >> 5);
    if (row >= ROWS_TOTAL) return;
    int lane = threadIdx.x & 31;
    float4 v = *reinterpret_cast<const float4*>(src + (size_t)row * DD + lane * 4);
    float s = v.x * v.x + v.y * v.y + v.z * v.z + v.w * v.w;
#pragma unroll
    for (int o = 16; o > 0; o >>= 1) s += __shfl_xor_sync(0xffffffffu, s, o);
    float inv = 1.0f / fmaxf(sqrtf(s), 1e-8f);

    float f[4] = {v.x * inv, v.y * inv, v.z * inv, v.w * inv};
    unsigned short hi[4], lo[4];
#pragma unroll
    for (int i = 0; i < 4; i++) {
        __nv_bfloat16 h = __float2bfloat16_rn(f[i]);
        __nv_bfloat16 l = __float2bfloat16_rn(f[i] - __bfloat162float(h));
        hi[i] = __bfloat16_as_ushort(h);
        lo[i] = __bfloat16_as_ushort(l);
    }
    uint2 hp = make_uint2((unsigned)hi[0] | ((unsigned)hi[1] << 16),
                          (unsigned)hi[2] | ((unsigned)hi[3] << 16));
    uint2 lp = make_uint2((unsigned)lo[0] | ((unsigned)lo[1] << 16),
                          (unsigned)lo[2] | ((unsigned)lo[3] << 16));
    size_t base = (size_t)row * KSP + lane * 4;
    *reinterpret_cast<uint2*>(dst + base)       = hp;  // hi half
    *reinterpret_cast<uint2*>(dst + base + 128) = lp;  // lo half
}

__global__ void init_counts_kernel(const float* __restrict__ leaf, float* __restrict__ counts) {
    int i = blockIdx.x * blockDim.x + threadIdx.x;
    if (i < CC * LL) counts[i] = leaf[i];
}

// ---------------- main fused GEMM + max/argmax (mma.sync) ----------------
// 256 threads, 8 warps (4m x 2n), warp tile 32x64, CTA tile 128x128, 2 CTAs/SM
__global__ __launch_bounds__(256, 2)
void cosmax_mma_kernel(float* __restrict__ cos_out, float* __restrict__ counts) {
    extern __shared__ char smem[];
    const unsigned sb = smem_u32(smem);
    const int tid  = threadIdx.x;
    const int lane = tid & 31;
    const int wid  = tid >> 5;
    const int wm   = wid >> 1;     // 0..3 : warp row (32 b-rows)
    const int wn   = wid & 1;      // 0..1 : category within CTA (64 cols)
    const int b0   = blockIdx.x * BT;
    const int l0   = blockIdx.y * NTT;

    float acc[2][8][4];
#pragma unroll
    for (int mt = 0; mt < 2; mt++)
#pragma unroll
        for (int nt = 0; nt < 8; nt++)
#pragma unroll
            for (int c = 0; c < 4; c++) acc[mt][nt][c] = 0.0f;

    // Load one 16KB slab (128 rows x 128B) with dense swizzled wavefronts:
    // 1024 16B-chunks, 256 threads x 4 chunks, consecutive lanes = consecutive chunks.
#define LOAD_SLAB(dstoff, gptr, r0, koff)                                                 \
    {                                                                                     \
        _Pragma("unroll")                                                                 \
        for (int j = 0; j < 4; j++) {                                                     \
            unsigned idx  = (unsigned)j * 256u + (unsigned)tid;                           \
            unsigned row  = idx >> 3;                                                     \
            unsigned col  = (idx & 7) * 16u;                                              \
            unsigned off_ = row * 128u + col;                                             \
            unsigned sw_  = off_ ^ ((row & 7) << 4);                                      \
            const char* g_ = (const char*)(gptr) +                                        \
                ((size_t)((r0) + row) * KSP + (koff)) * 2 + col;                          \
            asm volatile("cp.async.cg.shared.global [%0],[%1],16;"                        \
                         :: "r"(sb + (dstoff) + sw_), "l"(g_) : "memory");                \
        }                                                                                 \
    }
#define COMMIT() asm volatile("cp.async.commit_group;" ::: "memory")

    // Prologue: pinned hi slabs + first two streamed lo slabs
    LOAD_SLAB(PIN0, gA, b0, 0);   LOAD_SLAB(PIN2, gB, l0, 0);   COMMIT();  // C0
    LOAD_SLAB(PIN1, gA, b0, 64);  LOAD_SLAB(PIN3, gB, l0, 64);  COMMIT();  // C1
    LOAD_SLAB(RING0, gA, b0, 128);                              COMMIT();  // C2 (Alo0)
    LOAD_SLAB(RING1, gA, b0, 192);                              COMMIT();  // C3 (Alo1)

    // chunk -> (A slab, B slab)
    const unsigned AOFF[6] = {PIN0, PIN1, RING0, RING1, PIN0, PIN1};
    const unsigned BOFF[6] = {PIN2, PIN3, PIN2,  PIN3,  RING2, RING0};

#pragma unroll
    for (int c = 0; c < 6; c++) {
        if (c == 0)      cp_wait<3>();
        else if (c == 1) cp_wait<2>();
        else if (c == 5) cp_wait<0>();
        else             cp_wait<1>();
        __syncthreads();
        if (c == 2) { LOAD_SLAB(RING2, gB, l0, 128); COMMIT(); }  // C4 (Blo0)
        if (c == 3) { LOAD_SLAB(RING0, gB, l0, 192); COMMIT(); }  // C5 (Blo1)

        const unsigned sa = sb + AOFF[c];
        const unsigned sbB = sb + BOFF[c];
#pragma unroll
        for (int ks = 0; ks < 4; ks++) {
            unsigned af[2][4];
#pragma unroll
            for (int mt = 0; mt < 2; mt++) {
                int row = wm * 32 + mt * 16 + (lane & 15);
                unsigned off = (unsigned)row * 128u + (unsigned)ks * 32u + ((lane >> 4) * 16u);
                unsigned addr = sa + (off ^ ((unsigned)(row & 7) << 4));
                asm volatile("ldmatrix.sync.aligned.m8n8.x4.shared.b16 {%0,%1,%2,%3},[%4];"
                             : "=r"(af[mt][0]), "=r"(af[mt][1]), "=r"(af[mt][2]), "=r"(af[mt][3])
                             : "r"(addr));
            }
            unsigned bf[8][2];
#pragma unroll
            for (int np = 0; np < 4; np++) {
                int row = wn * 64 + np * 16 + ((lane & 16) >> 1) + (lane & 7);
                unsigned off = (unsigned)row * 128u + (unsigned)ks * 32u + ((lane & 8) ? 16u : 0u);
                unsigned addr = sbB + (off ^ ((unsigned)(row & 7) << 4));
                asm volatile("ldmatrix.sync.aligned.m8n8.x4.shared.b16 {%0,%1,%2,%3},[%4];"
                             : "=r"(bf[2*np][0]), "=r"(bf[2*np][1]),
                               "=r"(bf[2*np+1][0]), "=r"(bf[2*np+1][1])
                             : "r"(addr));
            }
#pragma unroll
            for (int mt = 0; mt < 2; mt++)
#pragma unroll
                for (int nt = 0; nt < 8; nt++)
                    asm volatile(
                        "mma.sync.aligned.m16n8k16.row.col.f32.bf16.bf16.f32 "
                        "{%0,%1,%2,%3},{%4,%5,%6,%7},{%8,%9},{%0,%1,%2,%3};"
                        : "+f"(acc[mt][nt][0]), "+f"(acc[mt][nt][1]),
                          "+f"(acc[mt][nt][2]), "+f"(acc[mt][nt][3])
                        : "r"(af[mt][0]), "r"(af[mt][1]), "r"(af[mt][2]), "r"(af[mt][3]),
                          "r"(bf[nt][0]), "r"(bf[nt][1]));
        }
    }

    // ---- epilogue: hist lives in reused smem (slab PIN0), zeroed post-mainloop ----
    float* hist = reinterpret_cast<float*>(smem);   // 128 floats
    __syncthreads();                 // all warps done reading smem tiles
    if (tid < 128) hist[tid] = 0.0f;
    __syncthreads();

    const int qcol = (lane & 3) * 2;
#pragma unroll
    for (int mt = 0; mt < 2; mt++) {
#pragma unroll
        for (int h = 0; h < 2; h++) {
            float m = __int_as_float(0xff800000);
            int arg = 0;
#pragma unroll
            for (int nt = 0; nt < 8; nt++) {
                float v0 = acc[mt][nt][2 * h];
                float v1 = acc[mt][nt][2 * h + 1];
                int c0 = nt * 8 + qcol;
                if (v0 > m) { m = v0; arg = c0; }
                if (v1 > m) { m = v1; arg = c0 + 1; }
            }
#pragma unroll
            for (int off = 1; off <= 2; off <<= 1) {
                float om = __shfl_xor_sync(0xffffffffu, m, off);
                int   oa = __shfl_xor_sync(0xffffffffu, arg, off);
                if (om > m || (om == m && oa < arg)) { m = om; arg = oa; }
            }
            if ((lane & 3) == 0) {
                int row = b0 + wm * 32 + mt * 16 + h * 8 + (lane >> 2);
                cos_out[(size_t)row * CC + blockIdx.y * 2 + wn] = m;
                atomicAdd(&hist[wn * LL + arg], 1.0f);
            }
        }
    }
    __syncthreads();
    if (tid < 128) {
        float v = hist[tid];
        if (v != 0.0f)
            atomicAdd(&counts[(blockIdx.y * 2 + (tid >> 6)) * LL + (tid & 63)], v);
    }
#undef LOAD_SLAB
#undef COMMIT
}

extern "C" void kernel_launch(void* const* d_in, const int* in_sizes, int n_in,
                              void* d_out, int out_size) {
    const float* x    = (const float*)d_in[0];
    const float* e    = (const float*)d_in[1];
    const float* leaf = (const float*)d_in[2];
    const int B = in_sizes[0] / DD;            // 65536

    float* cos_out = (float*)d_out;            // [B, C]
    float* counts  = cos_out + (size_t)B * CC; // [C, L]

    __nv_bfloat16 *pA, *pB;
    cudaGetSymbolAddress((void**)&pA, gA);
    cudaGetSymbolAddress((void**)&pB, gB);

    cudaFuncSetAttribute(cosmax_mma_kernel,
                         cudaFuncAttributeMaxDynamicSharedMemorySize, SMEM_TOTAL);

    split_pack_kernel<65536><<<B / 8, 256>>>(x, pA);
    split_pack_kernel<4096><<<(CC * LL) / 8, 256>>>(e, pB);
    init_counts_kernel<<<(CC * LL + 255) / 256, 256>>>(leaf, counts);

    dim3 grid(B / BT, (CC * LL) / NTT);        // (512, 32)
    cosmax_mma_kernel<<<grid, 256, SMEM_TOTAL>>>(cos_out, counts);
}